// round 17
// baseline (speedup 1.0000x reference)
#include <cuda_runtime.h>
#include <cuda_bf16.h>

#define BB 64
#define SS 2048
#define RR 1024
#define HH 512
#define NOWN 8                  // scores owned per thread in softmax prologue
#define NSPLIT 16               // S-chunks in k4 (1024 blocks -> 6.9 waves)
#define SCHUNK (SS / NSPLIT)    // 128
#define BPB 8                   // batches per producer block
#define NPROD 512               // producer blocks (64 j-groups x 8 b-groups)
#define MASKED_SCORE (-1e30f)   // masked entries: exp(v-mx) underflows to 0

// Scratch (allocation-free rule: __device__ globals)
__device__ float g_att_h[BB * HH];   // 128 KB
__device__ float g_score[BB * SS];   // 512 KB (masked scores)
__device__ int   g_done[BB / BPB];   // per-b-group producer counters (reset by k4)

__device__ __forceinline__ float fast_tanh(float x) {
    float y;
    asm("tanh.approx.f32 %0, %1;" : "=f"(y) : "f"(x));
    return y;
}

// ---------------------------------------------------------------------------
// K12: fused producer/consumer kernel. 1D grid of NPROD + B*(S/32) blocks.
//
// Producers (bid < NPROD): the frozen k1 body — att_h[b,j] = h.W[j]+bias for
// 8 batches (bg = bid>>6), W via direct L2-hot LDG.128, h rows in 32 KB smem.
// Being the LOWEST bids they are scheduled first (wave-1 is bid-ordered) and
// never wait -> no deadlock. Completion: __syncthreads, then thread 0
// __threadfence + atomicAdd(g_done[bg]) (threadFenceReduction pattern).
// Producers with bg<4 also zero d_out for k4's red.global accumulation.
//
// Consumers (bid >= NPROD): the k2 body — batch b = cid>>6 (b-group order,
// so early consumers match early producers), s-group sg = cid&63. Spin on
// g_done[b>>3]==64 with nanosleep, then stream 32 rows of p_att_feats:
// score = sum_h tanh(p+att_h)*w_alpha, mask applied at write (-1e30).
// The 256 MB k2 stream overlaps the producers' latency-bound tail.
// ---------------------------------------------------------------------------
__global__ void k12_fused(const float* __restrict__ h,
                          const float* __restrict__ W,
                          const float* __restrict__ bias,
                          const float* __restrict__ p,
                          const float* __restrict__ w_alpha,
                          const int* __restrict__ mask,
                          float* __restrict__ out) {
    __shared__ float smem_buf[BPB * RR];   // 32 KB, shared by both roles
    const int tid  = threadIdx.x;
    const int warp = tid >> 5;
    const int lane = tid & 31;

    if (blockIdx.x < NPROD) {
        // ----------------- PRODUCER (k1 body, frozen) -----------------
        const int jg = blockIdx.x & 63;
        const int bg = blockIdx.x >> 6;
        const int j  = jg * 8 + warp;
        const int b0 = bg * BPB;

        if (bg < 4)
            out[((size_t)bg * 64 + jg) * 256 + tid] = 0.f;

        const float4* Hg = (const float4*)(h + (size_t)b0 * RR);
#pragma unroll
        for (int k = 0; k < BPB; k++)
            ((float4*)smem_buf)[tid + k * 256] = Hg[tid + k * 256];

        __syncthreads();

        const float4* wr = (const float4*)(W + (size_t)j * RR);

        float a[BPB];
#pragma unroll
        for (int k = 0; k < BPB; k++) a[k] = 0.f;

#pragma unroll
        for (int i = 0; i < RR / 128; i++) {          // 8 iterations
            const int idx = i * 32 + lane;
            float4 w4 = wr[idx];                       // LDG.128, L2-hot
#pragma unroll
            for (int k = 0; k < BPB; k++) {
                float4 x = ((const float4*)(smem_buf + k * RR))[idx];
                a[k] += w4.x * x.x + w4.y * x.y + w4.z * x.z + w4.w * x.w;
            }
        }
#pragma unroll
        for (int o = 16; o; o >>= 1) {
#pragma unroll
            for (int k = 0; k < BPB; k++)
                a[k] += __shfl_down_sync(0xFFFFFFFFu, a[k], o);
        }
        if (lane == 0) {
            const float bj = bias[j];
#pragma unroll
            for (int k = 0; k < BPB; k++)
                g_att_h[(b0 + k) * HH + j] = a[k] + bj;
        }

        __syncthreads();                 // all warps' att_h stores issued
        if (tid == 0) {
            __threadfence();             // make them GPU-visible
            atomicAdd(&g_done[bg], 1);   // signal
        }
    } else {
        // ----------------- CONSUMER (k2 body) -----------------
        const int cid = blockIdx.x - NPROD;
        const int b   = cid >> 6;        // batch, in b-group order
        const int sg  = cid & 63;        // s-group of 32 rows

        // wait for this batch's b-group producers (64 of them)
        if (tid == 0) {
            while (atomicAdd(&g_done[b >> 3], 0) < 64)
                __nanosleep(128);
        }
        __syncthreads();
        __threadfence();                 // acquire side

        float* s_ah = smem_buf;          // 512 floats
        float* s_wa = smem_buf + HH;     // 512 floats
        for (int i = tid; i < HH / 4; i += blockDim.x) {
            ((float4*)s_ah)[i] = ((const float4*)(g_att_h + (size_t)b * HH))[i];
            ((float4*)s_wa)[i] = ((const float4*)w_alpha)[i];
        }
        __syncthreads();

        const int s0 = sg * 32 + warp * 4;   // this warp's first row

        const float4* pr0 = (const float4*)(p + ((size_t)b * SS + s0)     * HH);
        const float4* pr1 = (const float4*)(p + ((size_t)b * SS + s0 + 1) * HH);
        const float4* pr2 = (const float4*)(p + ((size_t)b * SS + s0 + 2) * HH);
        const float4* pr3 = (const float4*)(p + ((size_t)b * SS + s0 + 3) * HH);

        float acc0 = 0.f, acc1 = 0.f, acc2 = 0.f, acc3 = 0.f;
#pragma unroll
        for (int i = 0; i < HH / 128; i++) {           // 4 iterations
            const int idx = i * 32 + lane;
            float4 q0 = pr0[idx];
            float4 q1 = pr1[idx];
            float4 q2 = pr2[idx];
            float4 q3 = pr3[idx];
            const int k = idx * 4;
            const float a0 = s_ah[k],     w0 = s_wa[k];
            const float a1 = s_ah[k + 1], w1 = s_wa[k + 1];
            const float a2 = s_ah[k + 2], w2 = s_wa[k + 2];
            const float a3 = s_ah[k + 3], w3 = s_wa[k + 3];
            acc0 += fast_tanh(q0.x + a0) * w0 + fast_tanh(q0.y + a1) * w1
                  + fast_tanh(q0.z + a2) * w2 + fast_tanh(q0.w + a3) * w3;
            acc1 += fast_tanh(q1.x + a0) * w0 + fast_tanh(q1.y + a1) * w1
                  + fast_tanh(q1.z + a2) * w2 + fast_tanh(q1.w + a3) * w3;
            acc2 += fast_tanh(q2.x + a0) * w0 + fast_tanh(q2.y + a1) * w1
                  + fast_tanh(q2.z + a2) * w2 + fast_tanh(q2.w + a3) * w3;
            acc3 += fast_tanh(q3.x + a0) * w0 + fast_tanh(q3.y + a1) * w1
                  + fast_tanh(q3.z + a2) * w2 + fast_tanh(q3.w + a3) * w3;
        }
#pragma unroll
        for (int o = 16; o; o >>= 1) {
            acc0 += __shfl_down_sync(0xFFFFFFFFu, acc0, o);
            acc1 += __shfl_down_sync(0xFFFFFFFFu, acc1, o);
            acc2 += __shfl_down_sync(0xFFFFFFFFu, acc2, o);
            acc3 += __shfl_down_sync(0xFFFFFFFFu, acc3, o);
        }
        if (lane == 0) {
            const int base = b * SS + s0;
            g_score[base]     = mask[base]     ? acc0 : MASKED_SCORE;
            g_score[base + 1] = mask[base + 1] ? acc1 : MASKED_SCORE;
            g_score[base + 2] = mask[base + 2] ? acc2 : MASKED_SCORE;
            g_score[base + 3] = mask[base + 3] ? acc3 : MASKED_SCORE;
        }
    }
}

// ---------------------------------------------------------------------------
// K4: fused softmax + partial weighted sums over an S-chunk (S-split), with
// direct red.global accumulation into d_out. grid (B, NSPLIT=16), block 256.
// Also RESETS g_done for the next launch (stream-ordered after all consumers).
// Prologue: softmax from masked scores (e_i/sum == e_i*m_i/sum(e_j*m_j);
// masked scores are -1e30 so exp underflows to exactly 0).
// Main loop: dense 4 KB-row streaming of att_feats (512 MB total), unroll 8.
// ---------------------------------------------------------------------------
__global__ void k4_wsum(const float* __restrict__ feats,
                        float* __restrict__ out) {
    const int b   = blockIdx.x;
    const int sp  = blockIdx.y;
    const int s0  = sp * SCHUNK;
    const int tid = threadIdx.x;

    // reset producer flags for the next launch (one block, after k12 done)
    if (b == 0 && sp == 0 && tid < BB / BPB) g_done[tid] = 0;

    __shared__ float sw[SS];       // 8 KB: full weight row
    __shared__ float red[8];

    // --- load all SS scores for this batch row: thread tid owns tid + k*256
    float v[NOWN];
#pragma unroll
    for (int k = 0; k < NOWN; k++)
        v[k] = g_score[b * SS + k * 256 + tid];

    // --- block max
    float mx = v[0];
#pragma unroll
    for (int k = 1; k < NOWN; k++) mx = fmaxf(mx, v[k]);
#pragma unroll
    for (int o = 16; o; o >>= 1) mx = fmaxf(mx, __shfl_xor_sync(0xFFFFFFFFu, mx, o));
    if ((tid & 31) == 0) red[tid >> 5] = mx;
    __syncthreads();
    mx = fmaxf(fmaxf(fmaxf(red[0], red[1]), fmaxf(red[2], red[3])),
               fmaxf(fmaxf(red[4], red[5]), fmaxf(red[6], red[7])));
    __syncthreads();

    // --- exponentials + block sum (masked entries underflow to exactly 0)
    float e[NOWN];
    float sum = 0.f;
#pragma unroll
    for (int k = 0; k < NOWN; k++) {
        e[k] = __expf(v[k] - mx);
        sum += e[k];
    }
#pragma unroll
    for (int o = 16; o; o >>= 1) sum += __shfl_xor_sync(0xFFFFFFFFu, sum, o);
    if ((tid & 31) == 0) red[tid >> 5] = sum;
    __syncthreads();
    sum = red[0] + red[1] + red[2] + red[3] + red[4] + red[5] + red[6] + red[7];
    const float inv = 1.f / sum;

#pragma unroll
    for (int k = 0; k < NOWN; k++) sw[k * 256 + tid] = e[k] * inv;
    __syncthreads();

    // --- streaming weighted sum over this block's 128-row chunk
    const float4* base = (const float4*)(feats + ((size_t)b * SS + s0) * RR) + tid;
    const float*  wrow = sw + s0;

    float4 acc = make_float4(0.f, 0.f, 0.f, 0.f);
#pragma unroll 8
    for (int i = 0; i < SCHUNK; i++) {
        float4 f = base[(size_t)i * (RR / 4)];
        float w = wrow[i];
        acc.x += w * f.x; acc.y += w * f.y; acc.z += w * f.z; acc.w += w * f.w;
    }

    // --- accumulate directly into the output (REDG; 16 contributors/address)
    float* o = out + (size_t)b * RR + tid * 4;
    atomicAdd(o + 0, acc.x);
    atomicAdd(o + 1, acc.y);
    atomicAdd(o + 2, acc.z);
    atomicAdd(o + 3, acc.w);
}

// ---------------------------------------------------------------------------
extern "C" void kernel_launch(void* const* d_in, const int* in_sizes, int n_in,
                              void* d_out, int out_size) {
    const float* h         = (const float*)d_in[0];
    const float* att_feats = (const float*)d_in[1];
    const float* p_att     = (const float*)d_in[2];
    const int*   masks     = (const int*)  d_in[3];
    const float* W         = (const float*)d_in[4];
    const float* b_h2att   = (const float*)d_in[5];
    const float* w_alpha   = (const float*)d_in[6];
    // d_in[7] = b_alpha: unused (constant shift cancels in softmax)
    float*       out       = (float*)d_out;

    k12_fused <<<NPROD + BB * (SS / 32), 256>>>(h, W, b_h2att, p_att,
                                                w_alpha, masks, out);
    k4_wsum   <<<dim3(BB, NSPLIT),       256>>>(att_feats, out);
}